// round 3
// baseline (speedup 1.0000x reference)
#include <cuda_runtime.h>
#include <math.h>
#include <stdint.h>

#define NTAG 36
#define SEQ  512
#define HID  512
#define EMB  512
#define G4   2048   // 4*HID
#define DPIPE 4     // smem weight ring depth

// ---------------- device scratch (no allocations allowed) ----------------
__device__ __align__(16) float g_embeds[SEQ * EMB];        // 1 MB
__device__ __align__(16) float g_P[SEQ * G4];              // 4 MB: Wih@x + bih + bhh
__device__ __align__(16) float g_h[2][HID];
__device__ __align__(16) float g_c[HID];
__device__ int g_tag_list[NTAG * SEQ];
__device__ int g_tag_cnt[NTAG];
__device__ int g_flag[128];

__device__ __forceinline__ float sigmoidf_(float x) {
    return 1.0f / (1.0f + __expf(-x));
}
__device__ __forceinline__ float tanhf_(float x) {
    return 2.0f / (1.0f + __expf(-2.0f * x)) - 1.0f;
}
__device__ __forceinline__ void cp16(uint32_t smem_addr, const void* gptr) {
    asm volatile("cp.async.cg.shared.global [%0], [%1], 16;\n"
                 :: "r"(smem_addr), "l"(gptr));
}
__device__ __forceinline__ int ld_acq(const int* p) {
    int v;
    asm volatile("ld.global.acquire.gpu.b32 %0, [%1];" : "=r"(v) : "l"(p));
    return v;
}
__device__ __forceinline__ void st_rel(int* p, int v) {
    asm volatile("st.global.release.gpu.b32 [%0], %1;" :: "l"(p), "r"(v));
}

// ---------------- init: flags/counters, h0/c0, group tags by value ----------------
__global__ void k_init(const float* __restrict__ h0, const float* __restrict__ c0,
                       const int* __restrict__ tags) {
    int j = threadIdx.x;            // 512 threads
    g_h[0][j] = h0[j];
    g_c[j]    = c0[j];
    if (j < NTAG) g_tag_cnt[j] = 0;
    if (j < 128)  g_flag[j] = 0;
    __syncthreads();
    int tag = tags[j];
    int pos = atomicAdd(&g_tag_cnt[tag], 1);
    g_tag_list[tag * SEQ + pos] = j;
}

// ---------------- embedding gather ----------------
__global__ void k_embed(const int* __restrict__ x, const float* __restrict__ emb) {
    int t = blockIdx.x;             // grid 512, block 128
    int row = x[t];
    const float4* src = (const float4*)emb + (size_t)row * (EMB / 4);
    float4* dst = (float4*)g_embeds + (size_t)t * (EMB / 4);
    dst[threadIdx.x] = src[threadIdx.x];
}

// ---------------- precompute P[t] = Wih[tag_t] @ x_t + bih + bhh ----------------
// grid: (36 tags, 16 row-blocks of 128, 32 chunks of 16 timesteps). block 128.
__global__ void k_precompute(const float* __restrict__ Wih,
                             const float* __restrict__ bih,
                             const float* __restrict__ bhh) {
    __shared__ float4 Xs[16 * 128];   // 16 timesteps x 512 floats = 32 KB
    __shared__ int ts[16];
    int g   = blockIdx.x;
    int cnt = g_tag_cnt[g];
    int c0  = blockIdx.z * 16;
    if (c0 >= cnt) return;            // uniform per CTA
    int m   = min(16, cnt - c0);
    int tid = threadIdx.x;

    if (tid < 16) ts[tid] = (tid < m) ? g_tag_list[g * SEQ + c0 + tid] : 0;
    __syncthreads();

    #pragma unroll
    for (int it = 0; it < 16; ++it) {
        int i = it * 128 + tid;
        int n = i >> 7, kk = i & 127;
        Xs[i] = (n < m) ? ((const float4*)g_embeds)[(size_t)ts[n] * 128 + kk]
                        : make_float4(0.f, 0.f, 0.f, 0.f);
    }
    __syncthreads();

    int r = blockIdx.y * 128 + tid;   // 0..2047
    const float4* wrow = (const float4*)(Wih + ((size_t)g * G4 + r) * EMB);

    float acc[16];
    #pragma unroll
    for (int n = 0; n < 16; ++n) acc[n] = 0.f;

    #pragma unroll 2
    for (int kk = 0; kk < 128; ++kk) {
        float4 w = __ldg(wrow + kk);
        #pragma unroll
        for (int n = 0; n < 16; ++n) {
            float4 xv = Xs[n * 128 + kk];   // warp-broadcast, conflict-free
            acc[n] += w.x * xv.x + w.y * xv.y + w.z * xv.z + w.w * xv.w;
        }
    }

    float bias = bih[g * G4 + r] + bhh[g * G4 + r];
    for (int n = 0; n < m; ++n)
        g_P[(size_t)ts[n] * G4 + r] = acc[n] + bias;
}

// ---------------- persistent recurrent kernel ----------------
// grid 128 CTAs x 512 threads (16 warps). CTA b owns j in [4b,4b+4).
// warp w: jl=w&3, gate=w>>2 -> one 512-length dot per warp per step.
// Weights streamed GMEM->SMEM ring DPIPE steps ahead via cp.async.
__global__ void __launch_bounds__(512, 1) k_seq(const float* __restrict__ Whh,
                                                const int* __restrict__ tags_g) {
    extern __shared__ char dsm[];
    float* wsb   = (float*)dsm;                       // [DPIPE][16][512]  128 KB
    float* hs    = (float*)(dsm + DPIPE * 32768);     // [512]             2 KB
    int*   stags = (int*)  (dsm + DPIPE * 32768 + 2048);
    float* sred  = (float*)(dsm + DPIPE * 32768 + 4096);

    int tid  = threadIdx.x;
    int lane = tid & 31;
    int w    = tid >> 5;          // 0..15
    int jl   = w & 3;
    int gate = w >> 2;
    int b    = blockIdx.x;
    int row  = gate * HID + b * 4 + jl;   // W_hh row this warp owns

    stags[tid] = tags_g[tid];
    __syncthreads();

    float c = (tid < 4) ? g_c[b * 4 + tid] : 0.f;

    // prologue: fill slots 0..DPIPE-1 (one commit group per slot)
    #pragma unroll
    for (int s = 0; s < DPIPE; ++s) {
        const float* src = Whh + ((size_t)stags[s] * G4 + row) * HID;
        float* drow = wsb + s * (16 * 512) + w * 512;
        uint32_t dsa = (uint32_t)__cvta_generic_to_shared(drow);
        #pragma unroll
        for (int k = 0; k < 4; ++k)
            cp16(dsa + (lane + 32 * k) * 16, src + (lane + 32 * k) * 4);
        asm volatile("cp.async.commit_group;\n" ::: "memory");
    }

    for (int t = 0; t < SEQ; ++t) {
        int slot = t & (DPIPE - 1);

        // wait: slot t weights landed (self-copied, self-consumed)
        asm volatile("cp.async.wait_group %0;\n" :: "n"(DPIPE - 1) : "memory");

        // pull weights into registers (LDS, conflict-free)
        const float4* wr = (const float4*)(wsb + slot * (16 * 512) + w * 512);
        float4 a0 = wr[lane];
        float4 a1 = wr[lane + 32];
        float4 a2 = wr[lane + 64];
        float4 a3 = wr[lane + 96];

        // P prefetch (independent of h)
        float pi = 0.f, pf = 0.f, pg = 0.f, po = 0.f;
        if (tid < 4) {
            const float* Pt = g_P + (size_t)t * G4 + b * 4 + tid;
            pi = __ldg(Pt);
            pf = __ldg(Pt + 512);
            pg = __ldg(Pt + 1024);
            po = __ldg(Pt + 1536);
        }

        // warps 0-3: poll h-ready flags (all CTAs reached step t), stage h
        if (w < 4) {
            for (;;) {
                int f0 = ld_acq(&g_flag[lane]);
                int f1 = ld_acq(&g_flag[lane + 32]);
                int f2 = ld_acq(&g_flag[lane + 64]);
                int f3 = ld_acq(&g_flag[lane + 96]);
                int fmin = min(min(f0, f1), min(f2, f3));
                if (__all_sync(0xffffffffu, fmin >= t)) break;
            }
            const float4* hg = (const float4*)g_h[t & 1];
            ((float4*)hs)[w * 32 + lane] = __ldcg(hg + w * 32 + lane);
        }
        __syncthreads();   // hs visible; also orders LDS(ws) before cp.async reuse

        // dot: 512-length, weights in regs, h from smem
        const float4* hv4 = (const float4*)hs;
        float4 h0 = hv4[lane];
        float4 h1 = hv4[lane + 32];
        float4 h2 = hv4[lane + 64];
        float4 h3 = hv4[lane + 96];
        float acc = a0.x*h0.x + a0.y*h0.y + a0.z*h0.z + a0.w*h0.w;
        acc += a1.x*h1.x + a1.y*h1.y + a1.z*h1.z + a1.w*h1.w;
        acc += a2.x*h2.x + a2.y*h2.y + a2.z*h2.z + a2.w*h2.w;
        acc += a3.x*h3.x + a3.y*h3.y + a3.z*h3.z + a3.w*h3.w;
        #pragma unroll
        for (int off = 16; off; off >>= 1)
            acc += __shfl_down_sync(0xffffffffu, acc, off);
        if (lane == 0) sred[w] = acc;
        __syncthreads();

        // refill slot with weights for step t+DPIPE (slot now free: LDS done pre-BAR)
        if (t + DPIPE < SEQ) {
            const float* src = Whh + ((size_t)stags[t + DPIPE] * G4 + row) * HID;
            float* drow = wsb + slot * (16 * 512) + w * 512;
            uint32_t dsa = (uint32_t)__cvta_generic_to_shared(drow);
            #pragma unroll
            for (int k = 0; k < 4; ++k)
                cp16(dsa + (lane + 32 * k) * 16, src + (lane + 32 * k) * 4);
        }
        asm volatile("cp.async.commit_group;\n" ::: "memory");

        // gate math + publish h + release flag
        if (tid < 4) {
            float gi = sred[tid]      + pi;
            float gf = sred[4 + tid]  + pf;
            float gg = sred[8 + tid]  + pg;
            float go = sred[12 + tid] + po;
            float iv = sigmoidf_(gi);
            float fv = sigmoidf_(gf);
            float gv = tanhf_(gg);
            float ov = sigmoidf_(go);
            c = fv * c + iv * gv;
            g_h[(t + 1) & 1][b * 4 + tid] = ov * tanhf_(c);
            __syncwarp(0x0000000Fu);
            if (tid == 0) st_rel(&g_flag[b], t + 1);
        }
    }

    if (tid < 4) g_c[b * 4 + tid] = c;
}

// ---------------- final fc + sigmoid + pack outputs ----------------
__global__ void k_final(const float* __restrict__ Wfc, const float* __restrict__ bfc,
                        float* __restrict__ out, int out_size) {
    __shared__ float red[16];
    int tid = threadIdx.x;            // 512 threads
    float hv = g_h[0][tid];           // after step 511, h lives in buffer 0
    float v = hv * Wfc[tid];
    #pragma unroll
    for (int off = 16; off; off >>= 1) v += __shfl_down_sync(0xffffffffu, v, off);
    if ((tid & 31) == 0) red[tid >> 5] = v;
    __syncthreads();
    if (tid < 16) {
        float s = red[tid];
        #pragma unroll
        for (int off = 8; off; off >>= 1) s += __shfl_down_sync(0x0000ffffu, s, off);
        if (tid == 0 && out_size > 0)
            out[0] = sigmoidf_(s + bfc[0]);
    }
    if (1 + tid < out_size)   out[1 + tid]   = hv;
    if (513 + tid < out_size) out[513 + tid] = g_c[tid];
}

// ---------------- launcher ----------------
extern "C" void kernel_launch(void* const* d_in, const int* in_sizes, int n_in,
                              void* d_out, int out_size) {
    const int*   x    = (const int*)d_in[0];
    const int*   tags = (const int*)d_in[1];
    const float* h0   = (const float*)d_in[2];
    const float* c0   = (const float*)d_in[3];
    const float* emb  = (const float*)d_in[4];
    const float* Wih  = (const float*)d_in[5];
    const float* Whh  = (const float*)d_in[6];
    const float* bih  = (const float*)d_in[7];
    const float* bhh  = (const float*)d_in[8];
    const float* Wfc  = (const float*)d_in[9];
    const float* bfc  = (const float*)d_in[10];
    (void)in_sizes; (void)n_in;

    const int SMEM_SEQ = DPIPE * 32768 + 2048 + 2048 + 64;   // 135 KB
    cudaFuncSetAttribute(k_seq, cudaFuncAttributeMaxDynamicSharedMemorySize, SMEM_SEQ);

    k_init<<<1, 512>>>(h0, c0, tags);
    k_embed<<<512, 128>>>(x, emb);
    k_precompute<<<dim3(NTAG, 16, 32), 128>>>(Wih, bih, bhh);
    k_seq<<<128, 512, SMEM_SEQ>>>(Whh, tags);
    k_final<<<1, 512>>>(Wfc, bfc, (float*)d_out, out_size);
}

// round 4
// speedup vs baseline: 1.7159x; 1.7159x over previous
#include <cuda_runtime.h>
#include <math.h>
#include <stdint.h>

#define NTAG 36
#define SEQ  512
#define HID  512
#define EMB  512
#define G4   2048   // 4*HID
#define NCTA 128

// ---------------- device scratch (no allocations allowed) ----------------
__device__ __align__(16) float g_embeds[SEQ * EMB];        // 1 MB
__device__ __align__(16) float g_P[SEQ * G4];              // 4 MB: Wih@x + bih + bhh
__device__ __align__(16) float g_h[2][HID];
__device__ __align__(16) float g_c[HID];
__device__ int g_tag_list[NTAG * SEQ];
__device__ int g_tag_cnt[NTAG];
__device__ __align__(128) unsigned g_ctr;    // cumulative arrival counter (own line)
__device__ __align__(128) int g_step_flag;   // published step (own line, read-only polled)

__device__ __forceinline__ float sigmoidf_(float x) {
    return 1.0f / (1.0f + __expf(-x));
}
__device__ __forceinline__ float tanhf_(float x) {
    return 2.0f / (1.0f + __expf(-2.0f * x)) - 1.0f;
}

// ---------------- init: counters/flags, h0/c0, group tags by value ----------------
__global__ void k_init(const float* __restrict__ h0, const float* __restrict__ c0,
                       const int* __restrict__ tags) {
    int j = threadIdx.x;            // 512 threads
    g_h[0][j] = h0[j];
    g_c[j]    = c0[j];
    if (j < NTAG) g_tag_cnt[j] = 0;
    if (j == 0) { g_ctr = 0; g_step_flag = 0; }
    __syncthreads();
    int tag = tags[j];
    int pos = atomicAdd(&g_tag_cnt[tag], 1);
    g_tag_list[tag * SEQ + pos] = j;
}

// ---------------- embedding gather ----------------
__global__ void k_embed(const int* __restrict__ x, const float* __restrict__ emb) {
    int t = blockIdx.x;             // grid 512, block 128
    int row = x[t];
    const float4* src = (const float4*)emb + (size_t)row * (EMB / 4);
    float4* dst = (float4*)g_embeds + (size_t)t * (EMB / 4);
    dst[threadIdx.x] = src[threadIdx.x];
}

// ---------------- precompute P[t] = Wih[tag_t] @ x_t + bih + bhh ----------------
// (round-1 config: measured 148us)
__global__ void k_precompute(const float* __restrict__ Wih,
                             const float* __restrict__ bih,
                             const float* __restrict__ bhh) {
    __shared__ float4 Xs[16 * 128];   // 16 timesteps x 512 floats = 32 KB
    __shared__ int ts[16];
    int g   = blockIdx.x;
    int cnt = g_tag_cnt[g];
    int c0  = blockIdx.z * 16;
    if (c0 >= cnt) return;            // uniform per CTA
    int m   = min(16, cnt - c0);
    int tid = threadIdx.x;

    if (tid < 16) ts[tid] = (tid < m) ? g_tag_list[g * SEQ + c0 + tid] : 0;
    __syncthreads();

    #pragma unroll
    for (int it = 0; it < 16; ++it) {
        int i = it * 128 + tid;
        int n = i >> 7, kk = i & 127;
        Xs[i] = (n < m) ? ((const float4*)g_embeds)[(size_t)ts[n] * 128 + kk]
                        : make_float4(0.f, 0.f, 0.f, 0.f);
    }
    __syncthreads();

    int r = blockIdx.y * 128 + tid;   // 0..2047
    const float4* wrow = (const float4*)(Wih + ((size_t)g * G4 + r) * EMB);

    float acc[16];
    #pragma unroll
    for (int n = 0; n < 16; ++n) acc[n] = 0.f;

    #pragma unroll 2
    for (int kk = 0; kk < 128; ++kk) {
        float4 w = __ldg(wrow + kk);
        #pragma unroll
        for (int n = 0; n < 16; ++n) {
            float4 xv = Xs[n * 128 + kk];   // warp-broadcast, conflict-free
            acc[n] += w.x * xv.x + w.y * xv.y + w.z * xv.z + w.w * xv.w;
        }
    }

    float bias = bih[g * G4 + r] + bhh[g * G4 + r];
    for (int n = 0; n < m; ++n)
        g_P[(size_t)ts[n] * G4 + r] = acc[n] + bias;
}

// ---------------- persistent recurrent kernel ----------------
// 128 CTAs x 512 threads (16 warps). CTA b owns j in [4b,4b+4).
// warp w: jl=w&3, gate=w>>2 -> one 512-length dot per warp per step.
// Weights prefetched distance-1 in registers; h staged to smem by warps 0-3;
// barrier = per-CTA atomicAdd on one line + last-arriver publishes flag on another.
__global__ void __launch_bounds__(512, 1) k_seq(const float* __restrict__ Whh,
                                                const int* __restrict__ tags_g) {
    __shared__ float hs[HID];
    __shared__ float sred[16];
    __shared__ int stags[SEQ];

    int tid  = threadIdx.x;
    int lane = tid & 31;
    int w    = tid >> 5;          // 0..15
    int jl   = w & 3;
    int gate = w >> 2;
    int b    = blockIdx.x;
    int row  = gate * HID + b * 4 + jl;   // W_hh row this warp owns

    stags[tid] = tags_g[tid];
    __syncthreads();

    float c = (tid < 4) ? g_c[b * 4 + tid] : 0.f;

    // prefetch W row for t = 0
    const float4* wr = (const float4*)(Whh + ((size_t)stags[0] * G4 + row) * HID);
    float4 a0 = __ldg(wr + lane);
    float4 a1 = __ldg(wr + lane + 32);
    float4 a2 = __ldg(wr + lane + 64);
    float4 a3 = __ldg(wr + lane + 96);

    volatile int* flag = &g_step_flag;

    for (int t = 0; t < SEQ; ++t) {
        // P prefetch (independent of h_t) — issue before the wait
        float pi = 0.f, pf = 0.f, pg = 0.f, po = 0.f;
        if (tid < 4) {
            const float* Pt = g_P + (size_t)t * G4 + b * 4 + tid;
            pi = __ldg(Pt);
            pf = __ldg(Pt + 512);
            pg = __ldg(Pt + 1024);
            po = __ldg(Pt + 1536);
        }

        // wait: h_t published (single read-only line, 1 poller per CTA)
        if (tid == 0) {
            while (*flag < t) { }
            __threadfence();
        }
        __syncthreads();

        // stage h_t into smem (warps 0-3, via L2)
        if (w < 4)
            ((float4*)hs)[w * 32 + lane] = __ldcg((const float4*)g_h[t & 1] + w * 32 + lane);
        __syncthreads();

        // dot: weights in regs, h from smem
        const float4* hv4 = (const float4*)hs;
        float4 h0 = hv4[lane];
        float4 h1 = hv4[lane + 32];
        float4 h2 = hv4[lane + 64];
        float4 h3 = hv4[lane + 96];
        float acc = a0.x*h0.x + a0.y*h0.y + a0.z*h0.z + a0.w*h0.w;
        acc += a1.x*h1.x + a1.y*h1.y + a1.z*h1.z + a1.w*h1.w;
        acc += a2.x*h2.x + a2.y*h2.y + a2.z*h2.z + a2.w*h2.w;
        acc += a3.x*h3.x + a3.y*h3.y + a3.z*h3.z + a3.w*h3.w;

        // prefetch W row for t+1 (regs free; hides behind reduce+gates+barrier+poll)
        if (t + 1 < SEQ) {
            const float4* wr2 = (const float4*)(Whh + ((size_t)stags[t + 1] * G4 + row) * HID);
            a0 = __ldg(wr2 + lane);
            a1 = __ldg(wr2 + lane + 32);
            a2 = __ldg(wr2 + lane + 64);
            a3 = __ldg(wr2 + lane + 96);
        }

        // warp reduce + cross-warp combine
        #pragma unroll
        for (int off = 16; off; off >>= 1)
            acc += __shfl_down_sync(0xffffffffu, acc, off);
        if (lane == 0) sred[w] = acc;
        __syncthreads();

        // gates + publish h_{t+1}
        if (tid < 4) {
            float gi = sred[tid]      + pi;
            float gf = sred[4 + tid]  + pf;
            float gg = sred[8 + tid]  + pg;
            float go = sred[12 + tid] + po;
            float iv = sigmoidf_(gi);
            float fv = sigmoidf_(gf);
            float gv = tanhf_(gg);
            float ov = sigmoidf_(go);
            c = fv * c + iv * gv;
            __stcg(&g_h[(t + 1) & 1][b * 4 + tid], ov * tanhf_(c));
            __threadfence();
        }
        __syncthreads();   // all 4 h stores fenced to L2 before the arrive

        // arrive: cumulative counter on its own line; last arriver publishes flag
        if (tid == 0) {
            unsigned old = atomicAdd(&g_ctr, 1u);
            if (old == (unsigned)NCTA * (unsigned)(t + 1) - 1u) {
                __threadfence();
                *flag = t + 1;
            }
        }
    }

    if (tid < 4) g_c[b * 4 + tid] = c;
}

// ---------------- final fc + sigmoid + pack outputs ----------------
__global__ void k_final(const float* __restrict__ Wfc, const float* __restrict__ bfc,
                        float* __restrict__ out, int out_size) {
    __shared__ float red[16];
    int tid = threadIdx.x;            // 512 threads
    float hv = g_h[0][tid];           // after step 511, h lives in buffer 0
    float v = hv * Wfc[tid];
    #pragma unroll
    for (int off = 16; off; off >>= 1) v += __shfl_down_sync(0xffffffffu, v, off);
    if ((tid & 31) == 0) red[tid >> 5] = v;
    __syncthreads();
    if (tid < 16) {
        float s = red[tid];
        #pragma unroll
        for (int off = 8; off; off >>= 1) s += __shfl_down_sync(0x0000ffffu, s, off);
        if (tid == 0 && out_size > 0)
            out[0] = sigmoidf_(s + bfc[0]);
    }
    if (1 + tid < out_size)   out[1 + tid]   = hv;
    if (513 + tid < out_size) out[513 + tid] = g_c[tid];
}

// ---------------- launcher ----------------
extern "C" void kernel_launch(void* const* d_in, const int* in_sizes, int n_in,
                              void* d_out, int out_size) {
    const int*   x    = (const int*)d_in[0];
    const int*   tags = (const int*)d_in[1];
    const float* h0   = (const float*)d_in[2];
    const float* c0   = (const float*)d_in[3];
    const float* emb  = (const float*)d_in[4];
    const float* Wih  = (const float*)d_in[5];
    const float* Whh  = (const float*)d_in[6];
    const float* bih  = (const float*)d_in[7];
    const float* bhh  = (const float*)d_in[8];
    const float* Wfc  = (const float*)d_in[9];
    const float* bfc  = (const float*)d_in[10];
    (void)in_sizes; (void)n_in;

    k_init<<<1, 512>>>(h0, c0, tags);
    k_embed<<<512, 128>>>(x, emb);
    k_precompute<<<dim3(NTAG, 16, 32), 128>>>(Wih, bih, bhh);
    k_seq<<<NCTA, 512>>>(Whh, tags);
    k_final<<<1, 512>>>(Wfc, bfc, (float*)d_out, out_size);
}

// round 5
// speedup vs baseline: 2.3171x; 1.3504x over previous
#include <cuda_runtime.h>
#include <math.h>
#include <stdint.h>

#define NTAG 36
#define SEQ  512
#define HID  512
#define EMB  512
#define G4   2048   // 4*HID
#define NCTA 128

// ---------------- device scratch (no allocations allowed) ----------------
__device__ __align__(16) float g_embeds[SEQ * EMB];        // 1 MB
__device__ __align__(16) float g_P[SEQ * G4];              // 4 MB: Wih@x + bih + bhh
__device__ __align__(16) float g_h[2][HID];
__device__ __align__(16) float g_c[HID];
__device__ int g_tag_list[NTAG * SEQ];
__device__ int g_tag_cnt[NTAG];
__device__ __align__(128) unsigned g_ctr;   // cumulative arrival counter (R1-style)

__device__ __forceinline__ float sigmoidf_(float x) {
    return 1.0f / (1.0f + __expf(-x));
}
__device__ __forceinline__ float tanhf_(float x) {
    return 2.0f / (1.0f + __expf(-2.0f * x)) - 1.0f;
}
__device__ __forceinline__ void cp16(uint32_t smem_addr, const void* gptr) {
    asm volatile("cp.async.cg.shared.global [%0], [%1], 16;\n"
                 :: "r"(smem_addr), "l"(gptr));
}

// ---------------- init ----------------
__global__ void k_init(const float* __restrict__ h0, const float* __restrict__ c0,
                       const int* __restrict__ tags) {
    int j = threadIdx.x;            // 512 threads
    g_h[0][j] = h0[j];
    g_c[j]    = c0[j];
    if (j < NTAG) g_tag_cnt[j] = 0;
    if (j == 0)   g_ctr = 0;
    __syncthreads();
    int tag = tags[j];
    int pos = atomicAdd(&g_tag_cnt[tag], 1);
    g_tag_list[tag * SEQ + pos] = j;
}

// ---------------- embedding gather ----------------
__global__ void k_embed(const int* __restrict__ x, const float* __restrict__ emb) {
    int t = blockIdx.x;             // grid 512, block 128
    int row = x[t];
    const float4* src = (const float4*)emb + (size_t)row * (EMB / 4);
    float4* dst = (float4*)g_embeds + (size_t)t * (EMB / 4);
    dst[threadIdx.x] = src[threadIdx.x];
}

// ---------------- precompute P[t] = Wih[tag_t] @ x_t + bih + bhh (R1 config, 148us) ----
__global__ void k_precompute(const float* __restrict__ Wih,
                             const float* __restrict__ bih,
                             const float* __restrict__ bhh) {
    __shared__ float4 Xs[16 * 128];
    __shared__ int ts[16];
    int g   = blockIdx.x;
    int cnt = g_tag_cnt[g];
    int c0  = blockIdx.z * 16;
    if (c0 >= cnt) return;
    int m   = min(16, cnt - c0);
    int tid = threadIdx.x;

    if (tid < 16) ts[tid] = (tid < m) ? g_tag_list[g * SEQ + c0 + tid] : 0;
    __syncthreads();

    #pragma unroll
    for (int it = 0; it < 16; ++it) {
        int i = it * 128 + tid;
        int n = i >> 7, kk = i & 127;
        Xs[i] = (n < m) ? ((const float4*)g_embeds)[(size_t)ts[n] * 128 + kk]
                        : make_float4(0.f, 0.f, 0.f, 0.f);
    }
    __syncthreads();

    int r = blockIdx.y * 128 + tid;
    const float4* wrow = (const float4*)(Wih + ((size_t)g * G4 + r) * EMB);

    float acc[16];
    #pragma unroll
    for (int n = 0; n < 16; ++n) acc[n] = 0.f;

    #pragma unroll 2
    for (int kk = 0; kk < 128; ++kk) {
        float4 w = __ldg(wrow + kk);
        #pragma unroll
        for (int n = 0; n < 16; ++n) {
            float4 xv = Xs[n * 128 + kk];
            acc[n] += w.x * xv.x + w.y * xv.y + w.z * xv.z + w.w * xv.w;
        }
    }

    float bias = bih[g * G4 + r] + bhh[g * G4 + r];
    for (int n = 0; n < m; ++n)
        g_P[(size_t)ts[n] * G4 + r] = acc[n] + bias;
}

// ---------------- persistent recurrent kernel ----------------
// 128 CTAs x 256 threads (8 warps). CTA b owns j in [4b,4b+4).
// warp w: j = 4b + (w&3), gate pair p = (w>>2)*2 -> rows {p*512+j, (p+1)*512+j}.
// Weights: cp.async double-buffered smem ring, issued 2 steps ahead.
// Barrier: R1-style — tid0 atomicAdd cumulative ctr, tid0 polls the ctr directly.
__global__ void __launch_bounds__(256, 1) k_seq(const float* __restrict__ Whh,
                                                const int* __restrict__ tags_g) {
    extern __shared__ char dsm[];
    float*  wsb   = (float*)dsm;                         // [2][8 warps][1024]  64 KB
    float4* hs4   = (float4*)(dsm + 65536);              // h stage, 512 floats
    int*    stags = (int*)  (dsm + 65536 + 2048);        // 512 ints
    float*  sred  = (float*)(dsm + 65536 + 4096);        // 16 floats

    int tid  = threadIdx.x;
    int lane = tid & 31;
    int w    = tid >> 5;                 // 0..7
    int b    = blockIdx.x;
    int j    = b * 4 + (w & 3);
    int r0   = ((w >> 2) * 2) * HID + j; // first of the warp's two rows

    stags[tid]       = tags_g[tid];
    stags[tid + 256] = tags_g[tid + 256];
    __syncthreads();

    float c = (tid < 4) ? g_c[b * 4 + tid] : 0.f;

    uint32_t wbase = (uint32_t)__cvta_generic_to_shared(wsb + w * 1024);
    const size_t ROWSTRIDE = (size_t)HID;   // floats per row

    // prologue: fill slot 0 (t=0) and slot 1 (t=1), one commit group each
    #pragma unroll
    for (int s = 0; s < 2; ++s) {
        const float* s0 = Whh + ((size_t)stags[s] * G4 + r0) * ROWSTRIDE;
        const float* s1 = s0 + 512 * ROWSTRIDE;
        uint32_t d = wbase + s * 32768;
        #pragma unroll
        for (int k = 0; k < 4; ++k) {
            cp16(d +        (lane + 32 * k) * 16, s0 + (lane + 32 * k) * 4);
            cp16(d + 2048 + (lane + 32 * k) * 16, s1 + (lane + 32 * k) * 4);
        }
        asm volatile("cp.async.commit_group;\n" ::: "memory");
    }

    volatile unsigned* vb = &g_ctr;

    for (int t = 0; t < SEQ; ++t) {
        int slot = t & 1;

        // P prefetch (independent of h_t) — issue before the wait
        float pi = 0.f, pf = 0.f, pg = 0.f, po = 0.f;
        if (tid < 4) {
            const float* Pt = g_P + (size_t)t * G4 + b * 4 + tid;
            pi = __ldg(Pt);
            pf = __ldg(Pt + 512);
            pg = __ldg(Pt + 1024);
            po = __ldg(Pt + 1536);
        }

        // weights for step t are in smem ring (committed >=1 step ago)
        asm volatile("cp.async.wait_group 1;\n" ::: "memory");
        const float4* wr = (const float4*)(wsb + slot * 8192 + w * 1024);
        float4 b0 = wr[lane],       b1 = wr[lane + 32];
        float4 b2 = wr[lane + 64],  b3 = wr[lane + 96];
        float4 e0 = wr[128 + lane],      e1 = wr[128 + lane + 32];
        float4 e2 = wr[128 + lane + 64], e3 = wr[128 + lane + 96];

        // wait for h_t (direct counter poll, 1 thread)
        if (tid == 0) {
            unsigned target = (unsigned)NCTA * (unsigned)t;
            while (*vb < target) { }
            __threadfence();
        }
        __syncthreads();

        // stage h_t into smem (warps 0-3)
        if (w < 4)
            hs4[w * 32 + lane] = __ldcg((const float4*)g_h[t & 1] + w * 32 + lane);
        __syncthreads();

        // dot: 2 rows per warp, weights already in regs, h from smem
        float4 h0 = hs4[lane];
        float4 h1 = hs4[lane + 32];
        float4 h2 = hs4[lane + 64];
        float4 h3 = hs4[lane + 96];
        float acc0 = b0.x*h0.x + b0.y*h0.y + b0.z*h0.z + b0.w*h0.w
                   + b1.x*h1.x + b1.y*h1.y + b1.z*h1.z + b1.w*h1.w
                   + b2.x*h2.x + b2.y*h2.y + b2.z*h2.z + b2.w*h2.w
                   + b3.x*h3.x + b3.y*h3.y + b3.z*h3.z + b3.w*h3.w;
        float acc1 = e0.x*h0.x + e0.y*h0.y + e0.z*h0.z + e0.w*h0.w
                   + e1.x*h1.x + e1.y*h1.y + e1.z*h1.z + e1.w*h1.w
                   + e2.x*h2.x + e2.y*h2.y + e2.z*h2.z + e2.w*h2.w
                   + e3.x*h3.x + e3.y*h3.y + e3.z*h3.z + e3.w*h3.w;

        #pragma unroll
        for (int off = 16; off; off >>= 1) {
            acc0 += __shfl_down_sync(0xffffffffu, acc0, off);
            acc1 += __shfl_down_sync(0xffffffffu, acc1, off);
        }
        if (lane == 0) { sred[w * 2] = acc0; sred[w * 2 + 1] = acc1; }

        // refill this slot for step t+2 (slot's LDS reads are done)
        if (t + 2 < SEQ) {
            const float* s0 = Whh + ((size_t)stags[t + 2] * G4 + r0) * ROWSTRIDE;
            const float* s1 = s0 + 512 * ROWSTRIDE;
            uint32_t d = wbase + slot * 32768;
            #pragma unroll
            for (int k = 0; k < 4; ++k) {
                cp16(d +        (lane + 32 * k) * 16, s0 + (lane + 32 * k) * 4);
                cp16(d + 2048 + (lane + 32 * k) * 16, s1 + (lane + 32 * k) * 4);
            }
        }
        asm volatile("cp.async.commit_group;\n" ::: "memory");  // (maybe empty) keeps count
        __syncthreads();

        // gates + publish h_{t+1} + arrive  (gate g of j: sred[((g>>1)*4+j)*2+(g&1)])
        if (tid < 4) {
            float gi = sred[2 * tid]     + pi;
            float gf = sred[2 * tid + 1] + pf;
            float gg = sred[8 + 2 * tid] + pg;
            float go = sred[9 + 2 * tid] + po;
            float iv = sigmoidf_(gi);
            float fv = sigmoidf_(gf);
            float gv = tanhf_(gg);
            float ov = sigmoidf_(go);
            c = fv * c + iv * gv;
            __stcg(&g_h[(t + 1) & 1][b * 4 + tid], ov * tanhf_(c));
            __threadfence();
            __syncwarp(0x0000000Fu);
            if (tid == 0) atomicAdd(&g_ctr, 1u);
        }
    }

    if (tid < 4) g_c[b * 4 + tid] = c;
}

// ---------------- final fc + sigmoid + pack outputs ----------------
__global__ void k_final(const float* __restrict__ Wfc, const float* __restrict__ bfc,
                        float* __restrict__ out, int out_size) {
    __shared__ float red[16];
    int tid = threadIdx.x;            // 512 threads
    float hv = g_h[0][tid];           // after step 511, h lives in buffer 0
    float v = hv * Wfc[tid];
    #pragma unroll
    for (int off = 16; off; off >>= 1) v += __shfl_down_sync(0xffffffffu, v, off);
    if ((tid & 31) == 0) red[tid >> 5] = v;
    __syncthreads();
    if (tid < 16) {
        float s = red[tid];
        #pragma unroll
        for (int off = 8; off; off >>= 1) s += __shfl_down_sync(0x0000ffffu, s, off);
        if (tid == 0 && out_size > 0)
            out[0] = sigmoidf_(s + bfc[0]);
    }
    if (1 + tid < out_size)   out[1 + tid]   = hv;
    if (513 + tid < out_size) out[513 + tid] = g_c[tid];
}

// ---------------- launcher ----------------
extern "C" void kernel_launch(void* const* d_in, const int* in_sizes, int n_in,
                              void* d_out, int out_size) {
    const int*   x    = (const int*)d_in[0];
    const int*   tags = (const int*)d_in[1];
    const float* h0   = (const float*)d_in[2];
    const float* c0   = (const float*)d_in[3];
    const float* emb  = (const float*)d_in[4];
    const float* Wih  = (const float*)d_in[5];
    const float* Whh  = (const float*)d_in[6];
    const float* bih  = (const float*)d_in[7];
    const float* bhh  = (const float*)d_in[8];
    const float* Wfc  = (const float*)d_in[9];
    const float* bfc  = (const float*)d_in[10];
    (void)in_sizes; (void)n_in;

    const int SMEM_SEQ = 65536 + 2048 + 2048 + 128;   // 68.3 KB dynamic
    cudaFuncSetAttribute(k_seq, cudaFuncAttributeMaxDynamicSharedMemorySize, SMEM_SEQ);

    k_init<<<1, 512>>>(h0, c0, tags);
    k_embed<<<512, 128>>>(x, emb);
    k_precompute<<<dim3(NTAG, 16, 32), 128>>>(Wih, bih, bhh);
    k_seq<<<NCTA, 256, SMEM_SEQ>>>(Whh, tags);
    k_final<<<1, 512>>>(Wfc, bfc, (float*)d_out, out_size);
}

// round 6
// speedup vs baseline: 2.9884x; 1.2897x over previous
#include <cuda_runtime.h>
#include <math.h>
#include <stdint.h>

#define NTAG 36
#define SEQ  512
#define HID  512
#define EMB  512
#define G4   2048   // 4*HID
#define NCTA 128

// ---------------- device scratch (no allocations allowed) ----------------
__device__ __align__(16) float g_embeds[SEQ * EMB];        // 1 MB
__device__ __align__(16) float g_P[SEQ * G4];              // 4 MB: Wih@x + bih + bhh
__device__ __align__(16) float g_h[2][HID];
__device__ __align__(16) float g_c[HID];
__device__ int g_tag_list[NTAG * SEQ];
__device__ int g_tag_cnt[NTAG];
__device__ __align__(128) unsigned g_ctr;   // cumulative arrival counter

__device__ __forceinline__ float sigmoidf_(float x) {
    return 1.0f / (1.0f + __expf(-x));
}
__device__ __forceinline__ float tanhf_(float x) {
    return 2.0f / (1.0f + __expf(-2.0f * x)) - 1.0f;
}
__device__ __forceinline__ void cp16(uint32_t smem_addr, const void* gptr) {
    asm volatile("cp.async.cg.shared.global [%0], [%1], 16;\n"
                 :: "r"(smem_addr), "l"(gptr));
}
__device__ __forceinline__ unsigned ld_acq_u32(const unsigned* p) {
    unsigned v;
    asm volatile("ld.global.acquire.gpu.b32 %0, [%1];" : "=r"(v) : "l"(p));
    return v;
}
__device__ __forceinline__ void red_rel_add(unsigned* p, unsigned v) {
    asm volatile("red.global.release.gpu.add.u32 [%0], %1;" :: "l"(p), "r"(v) : "memory");
}

// ---------------- init ----------------
__global__ void k_init(const float* __restrict__ h0, const float* __restrict__ c0,
                       const int* __restrict__ tags) {
    int j = threadIdx.x;            // 512 threads
    g_h[0][j] = h0[j];
    g_c[j]    = c0[j];
    if (j < NTAG) g_tag_cnt[j] = 0;
    if (j == 0)   g_ctr = 0;
    __syncthreads();
    int tag = tags[j];
    int pos = atomicAdd(&g_tag_cnt[tag], 1);
    g_tag_list[tag * SEQ + pos] = j;
}

// ---------------- embedding gather ----------------
__global__ void k_embed(const int* __restrict__ x, const float* __restrict__ emb) {
    int t = blockIdx.x;             // grid 512, block 128
    int row = x[t];
    const float4* src = (const float4*)emb + (size_t)row * (EMB / 4);
    float4* dst = (float4*)g_embeds + (size_t)t * (EMB / 4);
    dst[threadIdx.x] = src[threadIdx.x];
}

// ---------------- precompute P[t] = Wih[tag_t] @ x_t + bih + bhh (148us config) ----
__global__ void k_precompute(const float* __restrict__ Wih,
                             const float* __restrict__ bih,
                             const float* __restrict__ bhh) {
    __shared__ float4 Xs[16 * 128];
    __shared__ int ts[16];
    int g   = blockIdx.x;
    int cnt = g_tag_cnt[g];
    int c0  = blockIdx.z * 16;
    if (c0 >= cnt) return;
    int m   = min(16, cnt - c0);
    int tid = threadIdx.x;

    if (tid < 16) ts[tid] = (tid < m) ? g_tag_list[g * SEQ + c0 + tid] : 0;
    __syncthreads();

    #pragma unroll
    for (int it = 0; it < 16; ++it) {
        int i = it * 128 + tid;
        int n = i >> 7, kk = i & 127;
        Xs[i] = (n < m) ? ((const float4*)g_embeds)[(size_t)ts[n] * 128 + kk]
                        : make_float4(0.f, 0.f, 0.f, 0.f);
    }
    __syncthreads();

    int r = blockIdx.y * 128 + tid;
    const float4* wrow = (const float4*)(Wih + ((size_t)g * G4 + r) * EMB);

    float acc[16];
    #pragma unroll
    for (int n = 0; n < 16; ++n) acc[n] = 0.f;

    #pragma unroll 2
    for (int kk = 0; kk < 128; ++kk) {
        float4 w = __ldg(wrow + kk);
        #pragma unroll
        for (int n = 0; n < 16; ++n) {
            float4 xv = Xs[n * 128 + kk];
            acc[n] += w.x * xv.x + w.y * xv.y + w.z * xv.z + w.w * xv.w;
        }
    }

    float bias = bih[g * G4 + r] + bhh[g * G4 + r];
    for (int n = 0; n < m; ++n)
        g_P[(size_t)ts[n] * G4 + r] = acc[n] + bias;
}

// ---------------- persistent recurrent kernel ----------------
// 128 CTAs x 256 threads (8 warps). CTA b owns j in [4b,4b+4).
// warp w: j = 4b + (w&3), gate pair p = (w>>2)*2 -> rows {p*512+j, (p+1)*512+j}.
// Weights: cp.async double-buffered smem ring, 2 steps ahead (R5, unchanged).
// Sync: producer tid0 packs h4 -> one STG.128 -> red.release arrive.
//       consumer warp0 acquire-polls ctr, then immediately ldcg h -> smem.
__global__ void __launch_bounds__(256, 1) k_seq(const float* __restrict__ Whh,
                                                const int* __restrict__ tags_g) {
    extern __shared__ char dsm[];
    float*  wsb   = (float*)dsm;                         // [2][8 warps][1024]  64 KB
    float4* hs4   = (float4*)(dsm + 65536);              // h stage, 512 floats
    int*    stags = (int*)  (dsm + 65536 + 2048);        // 512 ints
    float*  sred  = (float*)(dsm + 65536 + 4096);        // 16 floats

    int tid  = threadIdx.x;
    int lane = tid & 31;
    int w    = tid >> 5;                 // 0..7
    int b    = blockIdx.x;
    int j    = b * 4 + (w & 3);
    int r0   = ((w >> 2) * 2) * HID + j; // first of the warp's two rows

    stags[tid]       = tags_g[tid];
    stags[tid + 256] = tags_g[tid + 256];
    __syncthreads();

    float c = (tid < 4) ? g_c[b * 4 + tid] : 0.f;

    uint32_t wbase = (uint32_t)__cvta_generic_to_shared(wsb + w * 1024);
    const size_t ROWSTRIDE = (size_t)HID;

    // prologue: fill slot 0 (t=0) and slot 1 (t=1), one commit group each
    #pragma unroll
    for (int s = 0; s < 2; ++s) {
        const float* s0 = Whh + ((size_t)stags[s] * G4 + r0) * ROWSTRIDE;
        const float* s1 = s0 + 512 * ROWSTRIDE;
        uint32_t d = wbase + s * 32768;
        #pragma unroll
        for (int k = 0; k < 4; ++k) {
            cp16(d +        (lane + 32 * k) * 16, s0 + (lane + 32 * k) * 4);
            cp16(d + 2048 + (lane + 32 * k) * 16, s1 + (lane + 32 * k) * 4);
        }
        asm volatile("cp.async.commit_group;\n" ::: "memory");
    }

    for (int t = 0; t < SEQ; ++t) {
        int slot = t & 1;

        // P prefetch (independent of h_t) — first thing in the step
        float pi = 0.f, pf = 0.f, pg = 0.f, po = 0.f;
        if (tid < 4) {
            const float* Pt = g_P + (size_t)t * G4 + b * 4 + tid;
            pi = __ldg(Pt);
            pf = __ldg(Pt + 512);
            pg = __ldg(Pt + 1024);
            po = __ldg(Pt + 1536);
        }

        // weights for step t from smem ring
        asm volatile("cp.async.wait_group 1;\n" ::: "memory");
        const float4* wr = (const float4*)(wsb + slot * 8192 + w * 1024);
        float4 b0 = wr[lane],            b1 = wr[lane + 32];
        float4 b2 = wr[lane + 64],       b3 = wr[lane + 96];
        float4 e0 = wr[128 + lane],      e1 = wr[128 + lane + 32];
        float4 e2 = wr[128 + lane + 64], e3 = wr[128 + lane + 96];

        // refill this slot for step t+2 (regs hold the weights now)
        if (t + 2 < SEQ) {
            const float* s0 = Whh + ((size_t)stags[t + 2] * G4 + r0) * ROWSTRIDE;
            const float* s1 = s0 + 512 * ROWSTRIDE;
            uint32_t d = wbase + slot * 32768;
            #pragma unroll
            for (int k = 0; k < 4; ++k) {
                cp16(d +        (lane + 32 * k) * 16, s0 + (lane + 32 * k) * 4);
                cp16(d + 2048 + (lane + 32 * k) * 16, s1 + (lane + 32 * k) * 4);
            }
        }
        asm volatile("cp.async.commit_group;\n" ::: "memory");

        // warp 0: acquire-poll for h_t, then fetch h_t -> smem in the same warp
        if (w == 0) {
            unsigned target = (unsigned)NCTA * (unsigned)t;
            while (ld_acq_u32(&g_ctr) < target) { }
            const float4* hg = (const float4*)g_h[t & 1];
            hs4[lane]      = __ldcg(hg + lane);
            hs4[lane + 32] = __ldcg(hg + lane + 32);
            hs4[lane + 64] = __ldcg(hg + lane + 64);
            hs4[lane + 96] = __ldcg(hg + lane + 96);
        }
        __syncthreads();

        // dot: 2 rows per warp, weights in regs, h from smem
        float4 h0 = hs4[lane];
        float4 h1 = hs4[lane + 32];
        float4 h2 = hs4[lane + 64];
        float4 h3 = hs4[lane + 96];
        float acc0 = b0.x*h0.x + b0.y*h0.y + b0.z*h0.z + b0.w*h0.w
                   + b1.x*h1.x + b1.y*h1.y + b1.z*h1.z + b1.w*h1.w
                   + b2.x*h2.x + b2.y*h2.y + b2.z*h2.z + b2.w*h2.w
                   + b3.x*h3.x + b3.y*h3.y + b3.z*h3.z + b3.w*h3.w;
        float acc1 = e0.x*h0.x + e0.y*h0.y + e0.z*h0.z + e0.w*h0.w
                   + e1.x*h1.x + e1.y*h1.y + e1.z*h1.z + e1.w*h1.w
                   + e2.x*h2.x + e2.y*h2.y + e2.z*h2.z + e2.w*h2.w
                   + e3.x*h3.x + e3.y*h3.y + e3.z*h3.z + e3.w*h3.w;

        #pragma unroll
        for (int off = 16; off; off >>= 1) {
            acc0 += __shfl_down_sync(0xffffffffu, acc0, off);
            acc1 += __shfl_down_sync(0xffffffffu, acc1, off);
        }
        if (lane == 0) { sred[w * 2] = acc0; sred[w * 2 + 1] = acc1; }
        __syncthreads();

        // gates (tid 0..3) -> pack h4 in tid0 -> single STG.128 -> release arrive
        if (tid < 4) {
            float gi = sred[2 * tid]     + pi;
            float gf = sred[2 * tid + 1] + pf;
            float gg = sred[8 + 2 * tid] + pg;
            float go = sred[9 + 2 * tid] + po;
            float iv = sigmoidf_(gi);
            float fv = sigmoidf_(gf);
            float gv = tanhf_(gg);
            float ov = sigmoidf_(go);
            c = fv * c + iv * gv;
            float hv = ov * tanhf_(c);

            float h1v = __shfl_sync(0x0000000Fu, hv, 1);
            float h2v = __shfl_sync(0x0000000Fu, hv, 2);
            float h3v = __shfl_sync(0x0000000Fu, hv, 3);
            if (tid == 0) {
                float4 hq = make_float4(hv, h1v, h2v, h3v);
                *(float4*)&g_h[(t + 1) & 1][b * 4] = hq;   // one 16B store
                red_rel_add(&g_ctr, 1u);                   // release orders the store
            }
        }
    }

    if (tid < 4) g_c[b * 4 + tid] = c;
}

// ---------------- final fc + sigmoid + pack outputs ----------------
__global__ void k_final(const float* __restrict__ Wfc, const float* __restrict__ bfc,
                        float* __restrict__ out, int out_size) {
    __shared__ float red[16];
    int tid = threadIdx.x;            // 512 threads
    float hv = g_h[0][tid];           // after step 511, h lives in buffer 0
    float v = hv * Wfc[tid];
    #pragma unroll
    for (int off = 16; off; off >>= 1) v += __shfl_down_sync(0xffffffffu, v, off);
    if ((tid & 31) == 0) red[tid >> 5] = v;
    __syncthreads();
    if (tid < 16) {
        float s = red[tid];
        #pragma unroll
        for (int off = 8; off; off >>= 1) s += __shfl_down_sync(0x0000ffffu, s, off);
        if (tid == 0 && out_size > 0)
            out[0] = sigmoidf_(s + bfc[0]);
    }
    if (1 + tid < out_size)   out[1 + tid]   = hv;
    if (513 + tid < out_size) out[513 + tid] = g_c[tid];
}

// ---------------- launcher ----------------
extern "C" void kernel_launch(void* const* d_in, const int* in_sizes, int n_in,
                              void* d_out, int out_size) {
    const int*   x    = (const int*)d_in[0];
    const int*   tags = (const int*)d_in[1];
    const float* h0   = (const float*)d_in[2];
    const float* c0   = (const float*)d_in[3];
    const float* emb  = (const float*)d_in[4];
    const float* Wih  = (const float*)d_in[5];
    const float* Whh  = (const float*)d_in[6];
    const float* bih  = (const float*)d_in[7];
    const float* bhh  = (const float*)d_in[8];
    const float* Wfc  = (const float*)d_in[9];
    const float* bfc  = (const float*)d_in[10];
    (void)in_sizes; (void)n_in;

    const int SMEM_SEQ = 65536 + 2048 + 2048 + 128;   // 68.3 KB dynamic
    cudaFuncSetAttribute(k_seq, cudaFuncAttributeMaxDynamicSharedMemorySize, SMEM_SEQ);

    k_init<<<1, 512>>>(h0, c0, tags);
    k_embed<<<512, 128>>>(x, emb);
    k_precompute<<<dim3(NTAG, 16, 32), 128>>>(Wih, bih, bhh);
    k_seq<<<NCTA, 256, SMEM_SEQ>>>(Whh, tags);
    k_final<<<1, 512>>>(Wfc, bfc, (float*)d_out, out_size);
}

// round 7
// speedup vs baseline: 3.0293x; 1.0137x over previous
#include <cuda_runtime.h>
#include <math.h>
#include <stdint.h>

#define NTAG 36
#define SEQ  512
#define HID  512
#define EMB  512
#define G4   2048   // 4*HID
#define NCTA 128

// ---------------- device scratch (no allocations allowed) ----------------
__device__ __align__(16) float g_embeds[SEQ * EMB];        // 1 MB
__device__ __align__(16) float g_P[SEQ * G4];              // 4 MB: Wih@x + bih + bhh
__device__ __align__(16) float g_h[2][HID];
__device__ __align__(16) float g_c[HID];
__device__ int g_tag_list[NTAG * SEQ];
__device__ int g_tag_cnt[NTAG];
__device__ __align__(128) unsigned g_ctr;   // cumulative arrival counter

__device__ __forceinline__ float sigmoidf_(float x) {
    return 1.0f / (1.0f + __expf(-x));
}
__device__ __forceinline__ float tanhf_(float x) {
    return 2.0f / (1.0f + __expf(-2.0f * x)) - 1.0f;
}
__device__ __forceinline__ void cp16(uint32_t smem_addr, const void* gptr) {
    asm volatile("cp.async.cg.shared.global [%0], [%1], 16;\n"
                 :: "r"(smem_addr), "l"(gptr));
}
__device__ __forceinline__ unsigned ld_acq_u32(const unsigned* p) {
    unsigned v;
    asm volatile("ld.global.acquire.gpu.b32 %0, [%1];" : "=r"(v) : "l"(p));
    return v;
}
__device__ __forceinline__ void red_rel_add(unsigned* p, unsigned v) {
    asm volatile("red.global.release.gpu.add.u32 [%0], %1;" :: "l"(p), "r"(v) : "memory");
}

// ---------------- init ----------------
__global__ void k_init(const float* __restrict__ h0, const float* __restrict__ c0,
                       const int* __restrict__ tags) {
    int j = threadIdx.x;            // 512 threads
    g_h[0][j] = h0[j];
    g_c[j]    = c0[j];
    if (j < NTAG) g_tag_cnt[j] = 0;
    if (j == 0)   g_ctr = 0;
    __syncthreads();
    int tag = tags[j];
    int pos = atomicAdd(&g_tag_cnt[tag], 1);
    g_tag_list[tag * SEQ + pos] = j;
}

// ---------------- embedding gather ----------------
__global__ void k_embed(const int* __restrict__ x, const float* __restrict__ emb) {
    int t = blockIdx.x;             // grid 512, block 128
    int row = x[t];
    const float4* src = (const float4*)emb + (size_t)row * (EMB / 4);
    float4* dst = (float4*)g_embeds + (size_t)t * (EMB / 4);
    dst[threadIdx.x] = src[threadIdx.x];
}

// ---------------- precompute P[t] = Wih[tag_t] @ x_t + bih + bhh (148us config) ----
__global__ void k_precompute(const float* __restrict__ Wih,
                             const float* __restrict__ bih,
                             const float* __restrict__ bhh) {
    __shared__ float4 Xs[16 * 128];
    __shared__ int ts[16];
    int g   = blockIdx.x;
    int cnt = g_tag_cnt[g];
    int c0  = blockIdx.z * 16;
    if (c0 >= cnt) return;
    int m   = min(16, cnt - c0);
    int tid = threadIdx.x;

    if (tid < 16) ts[tid] = (tid < m) ? g_tag_list[g * SEQ + c0 + tid] : 0;
    __syncthreads();

    #pragma unroll
    for (int it = 0; it < 16; ++it) {
        int i = it * 128 + tid;
        int n = i >> 7, kk = i & 127;
        Xs[i] = (n < m) ? ((const float4*)g_embeds)[(size_t)ts[n] * 128 + kk]
                        : make_float4(0.f, 0.f, 0.f, 0.f);
    }
    __syncthreads();

    int r = blockIdx.y * 128 + tid;
    const float4* wrow = (const float4*)(Wih + ((size_t)g * G4 + r) * EMB);

    float acc[16];
    #pragma unroll
    for (int n = 0; n < 16; ++n) acc[n] = 0.f;

    #pragma unroll 2
    for (int kk = 0; kk < 128; ++kk) {
        float4 w = __ldg(wrow + kk);
        #pragma unroll
        for (int n = 0; n < 16; ++n) {
            float4 xv = Xs[n * 128 + kk];
            acc[n] += w.x * xv.x + w.y * xv.y + w.z * xv.z + w.w * xv.w;
        }
    }

    float bias = bih[g * G4 + r] + bhh[g * G4 + r];
    for (int n = 0; n < m; ++n)
        g_P[(size_t)ts[n] * G4 + r] = acc[n] + bias;
}

// ---------------- persistent recurrent kernel (warp-specialized) ----------------
// 128 CTAs x 288 threads (9 warps). CTA b owns j in [4b,4b+4).
// warp 0: sync/h/gates only. warps 1-8 (idx=w-1): rows {p*512+j,(p+1)*512+j},
//   j = 4b+(idx&3), p = (idx>>2)*2. Weights: cp.async double-buffered smem ring.
// Sync: tid0 packs h4 -> STG.128 -> red.release; warp0 acquire-polls then ldcg h.
__global__ void __launch_bounds__(288, 1) k_seq(const float* __restrict__ Whh,
                                                const int* __restrict__ tags_g) {
    extern __shared__ char dsm[];
    float*  wsb   = (float*)dsm;                         // [2][8 warps][1024]  64 KB
    float4* hs4   = (float4*)(dsm + 65536);              // h stage, 512 floats
    int*    stags = (int*)  (dsm + 65536 + 2048);        // 512 ints
    float*  sred  = (float*)(dsm + 65536 + 4096);        // 16 floats

    int tid  = threadIdx.x;
    int lane = tid & 31;
    int w    = tid >> 5;                 // 0..8
    int b    = blockIdx.x;
    int idx  = w - 1;                    // compute-warp index 0..7 (w>=1)
    int j    = b * 4 + (idx & 3);
    int r0   = ((idx >> 2) * 2) * HID + j;

    for (int i = tid; i < SEQ; i += 288) stags[i] = tags_g[i];
    __syncthreads();

    float c = (tid < 4) ? g_c[b * 4 + tid] : 0.f;

    uint32_t wbase = 0;
    const size_t ROWSTRIDE = (size_t)HID;
    if (w > 0) {
        wbase = (uint32_t)__cvta_generic_to_shared(wsb + idx * 1024);
        // prologue: fill slot 0 (t=0) and slot 1 (t=1), one commit group each
        #pragma unroll
        for (int s = 0; s < 2; ++s) {
            const float* s0 = Whh + ((size_t)stags[s] * G4 + r0) * ROWSTRIDE;
            const float* s1 = s0 + 512 * ROWSTRIDE;
            uint32_t d = wbase + s * 32768;
            #pragma unroll
            for (int k = 0; k < 4; ++k) {
                cp16(d +        (lane + 32 * k) * 16, s0 + (lane + 32 * k) * 4);
                cp16(d + 2048 + (lane + 32 * k) * 16, s1 + (lane + 32 * k) * 4);
            }
            asm volatile("cp.async.commit_group;\n" ::: "memory");
        }
    }

    float pi = 0.f, pf = 0.f, pg = 0.f, po = 0.f;

    for (int t = 0; t < SEQ; ++t) {
        int slot = t & 1;

        if (w == 0) {
            // P prefetch (lanes 0-3), then immediately poll — nothing else first
            if (lane < 4) {
                const float* Pt = g_P + (size_t)t * G4 + b * 4 + lane;
                pi = __ldg(Pt);
                pf = __ldg(Pt + 512);
                pg = __ldg(Pt + 1024);
                po = __ldg(Pt + 1536);
            }
            unsigned target = (unsigned)NCTA * (unsigned)t;
            while (ld_acq_u32(&g_ctr) < target) { }
            const float4* hg = (const float4*)g_h[t & 1];
            hs4[lane]      = __ldcg(hg + lane);
            hs4[lane + 32] = __ldcg(hg + lane + 32);
            hs4[lane + 64] = __ldcg(hg + lane + 64);
            hs4[lane + 96] = __ldcg(hg + lane + 96);
            __syncthreads();   // bar1: h staged
            __syncthreads();   // bar2: sred ready
            if (lane < 4) {
                float gi = sred[2 * lane]     + pi;
                float gf = sred[2 * lane + 1] + pf;
                float gg = sred[8 + 2 * lane] + pg;
                float go = sred[9 + 2 * lane] + po;
                float iv = sigmoidf_(gi);
                float fv = sigmoidf_(gf);
                float gv = tanhf_(gg);
                float ov = sigmoidf_(go);
                c = fv * c + iv * gv;
                float hv = ov * tanhf_(c);
                float h1v = __shfl_sync(0x0000000Fu, hv, 1);
                float h2v = __shfl_sync(0x0000000Fu, hv, 2);
                float h3v = __shfl_sync(0x0000000Fu, hv, 3);
                if (lane == 0) {
                    float4 hq = make_float4(hv, h1v, h2v, h3v);
                    *(float4*)&g_h[(t + 1) & 1][b * 4] = hq;   // one 16B store
                    red_rel_add(&g_ctr, 1u);                   // release orders it
                }
            }
        } else {
            // compute warps: weight LDS + refill happen while warp 0 polls
            asm volatile("cp.async.wait_group 1;\n" ::: "memory");
            const float4* wr = (const float4*)(wsb + slot * 8192 + idx * 1024);
            float4 b0 = wr[lane],            b1 = wr[lane + 32];
            float4 b2 = wr[lane + 64],       b3 = wr[lane + 96];
            float4 e0 = wr[128 + lane],      e1 = wr[128 + lane + 32];
            float4 e2 = wr[128 + lane + 64], e3 = wr[128 + lane + 96];

            if (t + 2 < SEQ) {
                const float* s0 = Whh + ((size_t)stags[t + 2] * G4 + r0) * ROWSTRIDE;
                const float* s1 = s0 + 512 * ROWSTRIDE;
                uint32_t d = wbase + slot * 32768;
                #pragma unroll
                for (int k = 0; k < 4; ++k) {
                    cp16(d +        (lane + 32 * k) * 16, s0 + (lane + 32 * k) * 4);
                    cp16(d + 2048 + (lane + 32 * k) * 16, s1 + (lane + 32 * k) * 4);
                }
            }
            asm volatile("cp.async.commit_group;\n" ::: "memory");

            __syncthreads();   // bar1: wait for h in smem

            float4 h0 = hs4[lane];
            float4 h1 = hs4[lane + 32];
            float4 h2 = hs4[lane + 64];
            float4 h3 = hs4[lane + 96];
            float acc0 = b0.x*h0.x + b0.y*h0.y + b0.z*h0.z + b0.w*h0.w
                       + b1.x*h1.x + b1.y*h1.y + b1.z*h1.z + b1.w*h1.w
                       + b2.x*h2.x + b2.y*h2.y + b2.z*h2.z + b2.w*h2.w
                       + b3.x*h3.x + b3.y*h3.y + b3.z*h3.z + b3.w*h3.w;
            float acc1 = e0.x*h0.x + e0.y*h0.y + e0.z*h0.z + e0.w*h0.w
                       + e1.x*h1.x + e1.y*h1.y + e1.z*h1.z + e1.w*h1.w
                       + e2.x*h2.x + e2.y*h2.y + e2.z*h2.z + e2.w*h2.w
                       + e3.x*h3.x + e3.y*h3.y + e3.z*h3.z + e3.w*h3.w;
            #pragma unroll
            for (int off = 16; off; off >>= 1) {
                acc0 += __shfl_down_sync(0xffffffffu, acc0, off);
                acc1 += __shfl_down_sync(0xffffffffu, acc1, off);
            }
            if (lane == 0) { sred[idx * 2] = acc0; sred[idx * 2 + 1] = acc1; }
            __syncthreads();   // bar2: sred published
        }
    }

    if (tid < 4) g_c[b * 4 + tid] = c;
}

// ---------------- final fc + sigmoid + pack outputs ----------------
__global__ void k_final(const float* __restrict__ Wfc, const float* __restrict__ bfc,
                        float* __restrict__ out, int out_size) {
    __shared__ float red[16];
    int tid = threadIdx.x;            // 512 threads
    float hv = g_h[0][tid];           // after step 511, h lives in buffer 0
    float v = hv * Wfc[tid];
    #pragma unroll
    for (int off = 16; off; off >>= 1) v += __shfl_down_sync(0xffffffffu, v, off);
    if ((tid & 31) == 0) red[tid >> 5] = v;
    __syncthreads();
    if (tid < 16) {
        float s = red[tid];
        #pragma unroll
        for (int off = 8; off; off >>= 1) s += __shfl_down_sync(0x0000ffffu, s, off);
        if (tid == 0 && out_size > 0)
            out[0] = sigmoidf_(s + bfc[0]);
    }
    if (1 + tid < out_size)   out[1 + tid]   = hv;
    if (513 + tid < out_size) out[513 + tid] = g_c[tid];
}

// ---------------- launcher ----------------
extern "C" void kernel_launch(void* const* d_in, const int* in_sizes, int n_in,
                              void* d_out, int out_size) {
    const int*   x    = (const int*)d_in[0];
    const int*   tags = (const int*)d_in[1];
    const float* h0   = (const float*)d_in[2];
    const float* c0   = (const float*)d_in[3];
    const float* emb  = (const float*)d_in[4];
    const float* Wih  = (const float*)d_in[5];
    const float* Whh  = (const float*)d_in[6];
    const float* bih  = (const float*)d_in[7];
    const float* bhh  = (const float*)d_in[8];
    const float* Wfc  = (const float*)d_in[9];
    const float* bfc  = (const float*)d_in[10];
    (void)in_sizes; (void)n_in;

    const int SMEM_SEQ = 65536 + 2048 + 2048 + 128;   // 68.3 KB dynamic
    cudaFuncSetAttribute(k_seq, cudaFuncAttributeMaxDynamicSharedMemorySize, SMEM_SEQ);

    k_init<<<1, 512>>>(h0, c0, tags);
    k_embed<<<512, 128>>>(x, emb);
    k_precompute<<<dim3(NTAG, 16, 32), 128>>>(Wih, bih, bhh);
    k_seq<<<NCTA, 288, SMEM_SEQ>>>(Whh, tags);
    k_final<<<1, 512>>>(Wfc, bfc, (float*)d_out, out_size);
}